// round 15
// baseline (speedup 1.0000x reference)
#include <cuda_runtime.h>

// ---------------------------------------------------------------------------
// MultiGVPConvLayer fused, v14: edge vector outputs staged into sout rows
// (cols 128..175) and scattered via the per-edge coalesced red4 path
// (2 contiguous red4/edge instead of ~32-sector scattered red4s).
// Node = v13 (single-tf32 A, B from L2). Edge = launch #4 (ncu).
//   Output: concat( out_s [N,128], out_v [N,48] ) float32
// ---------------------------------------------------------------------------

#define NMAX 50000
#define TE 64
#define EPAD 36
#define SPAD 180

__device__ float  g_agg[(size_t)NMAX * 176];  // per-node [128 s | 48 v] sums
__device__ float  g_cnt[NMAX];                // in-degree counts
__device__ float2 g_wesB[2048];               // edge B-frags [kt4][ntg16][lane32] tf32
__device__ float2 g_wB[16384];                // node B-frags [kt16][ntg32][lane32] tf32
__device__ float  g_wVT[48 * 96];             // [k][ wnv_out(48) | wrv_out(48) ]

__device__ __forceinline__ float sigf(float x) { return 1.f / (1.f + __expf(-x)); }

__device__ __forceinline__ void red4(float* p, float4 v) {
    asm volatile("red.global.add.v4.f32 [%0], {%1,%2,%3,%4};"
                 :: "l"(p), "f"(v.x), "f"(v.y), "f"(v.z), "f"(v.w) : "memory");
}

__device__ __forceinline__ unsigned tf32u(float f) {
    unsigned u;
    asm("cvt.rna.tf32.f32 %0, %1;" : "=r"(u) : "f"(f));
    return u;
}
__device__ __forceinline__ float tf32f(float f) { return __uint_as_float(tf32u(f)); }

__device__ __forceinline__ void mma_tf32(float* d, const unsigned* a, const unsigned* b) {
    asm volatile(
        "mma.sync.aligned.m16n8k8.row.col.f32.tf32.tf32.f32 "
        "{%0,%1,%2,%3}, {%4,%5,%6,%7}, {%8,%9}, {%0,%1,%2,%3};"
        : "+f"(d[0]), "+f"(d[1]), "+f"(d[2]), "+f"(d[3])
        : "r"(a[0]), "r"(a[1]), "r"(a[2]), "r"(a[3]), "r"(b[0]), "r"(b[1]));
}

// ---------------------------------------------------------------------------
__global__ void prep_kernel(const float* __restrict__ wes,     // launch #1
                            const float* __restrict__ wns, const float* __restrict__ wrs,
                            const float* __restrict__ wnv, const float* __restrict__ wrv)
{
    int t = blockIdx.x * 256 + threadIdx.x;
    if (t < 2048) {             // edge B frags
        int lane = t & 31, ntg = (t >> 5) & 15, kt = t >> 9;
        int g = lane >> 2, tig = lane & 3;
        int k = kt * 8 + tig;
        int n = ntg * 8 + g;
        g_wesB[t] = make_float2(tf32f(wes[n * 32 + k]), tf32f(wes[n * 32 + k + 4]));
    }
    if (t < 16384) {            // node B frags
        int lane = t & 31, ntg = (t >> 5) & 31, kt = t >> 10;
        int g = lane >> 2, tig = lane & 3;
        int k = kt * 8 + tig;
        int n = ntg * 8 + g;
        const float* srow = (n < 128) ? (wns + n * 128) : (wrs + (n - 128) * 128);
        g_wB[t] = make_float2(tf32f(srow[k]), tf32f(srow[k + 4]));
    }
    if (t < 48 * 48) { int o = t / 48, k = t % 48; g_wVT[k * 96 + o] = wnv[t];
                                                   g_wVT[k * 96 + 48 + o] = wrv[t]; }
}

__global__ void zero_agg_kernel(int Nn)                        // launch #2
{
    size_t t = (size_t)blockIdx.x * 256 + threadIdx.x;
    if (t < (size_t)Nn * 44) ((float4*)g_agg)[t] = make_float4(0.f, 0.f, 0.f, 0.f);
}
__global__ void zero_cnt_kernel(int Nn)                        // launch #3
{
    int t = blockIdx.x * 256 + threadIdx.x;
    if (t < Nn) g_cnt[t] = 0.f;
}

// ---------------------------------------------------------------------------
// Edge kernel (launch #4 -> ncu). 64 edges / 256 threads.
// A single tf32; B via __ldg from L2. sout row = [128 scalar | 48 vector];
// one unified coalesced scatter: red4 x (32 lanes) + red4 x (12 lanes) per edge.
// ---------------------------------------------------------------------------
__global__ __launch_bounds__(256) void edge_kernel(
    const float* __restrict__ edge_s, const float* __restrict__ edge_v,
    const int* __restrict__ edge_index,
    const float* __restrict__ bes, const float* __restrict__ wev,
    const float* __restrict__ bev, int E)
{
    __shared__ char  uni[46080];         // es_h [64][36] overlaid by sout [64][180]
    __shared__ float ev_sh[TE * 3];
    __shared__ int   dst_sh[TE];
    __shared__ float gate_sh[TE * 16];
    __shared__ float bes_sh[128];
    __shared__ float wev_sh[144];
    __shared__ float bev_sh[48];

    float* es_h = (float*)uni;                         // [64][36] during mma
    float* sout = (float*)uni;                         // [64][180] after mma

    const int tid  = threadIdx.x;
    const int lane = tid & 31;
    const int w    = tid >> 5;
    const int e0   = blockIdx.x * TE;
    const int nE   = min(TE, E - e0);

    // ---- stage edge_s (tf32, float4) + params
    {
        const float4* s4 = (const float4*)(edge_s + (size_t)e0 * 32);
        for (int i = tid; i < TE * 8; i += 256) {
            int e = i >> 3, c = (i & 7) * 4;
            float4 v = (e < nE) ? s4[i] : make_float4(0.f, 0.f, 0.f, 0.f);
            float4 h;
            h.x = tf32f(v.x); h.y = tf32f(v.y); h.z = tf32f(v.z); h.w = tf32f(v.w);
            *(float4*)(es_h + e * EPAD + c) = h;
        }
    }
    if (tid < TE * 3) { int e = tid / 3; ev_sh[tid] = (e < nE) ? edge_v[(size_t)e0 * 3 + tid] : 0.f; }
    if (tid < TE) {
        int d = -1;
        if (tid < nE) { d = edge_index[E + e0 + tid]; atomicAdd(&g_cnt[d], 1.f); }
        dst_sh[tid] = d;
    }
    if (tid < 128) bes_sh[tid] = bes[tid];
    if (tid < 144) wev_sh[tid] = wev[tid];
    if (tid < 48)  bev_sh[tid] = bev[tid];
    __syncthreads();

    // ---- mma mainloop (A single tf32; B via __ldg from L2)
    const int g   = lane >> 2;
    const int tig = lane & 3;
    const int m0  = (w >> 1) * 16;
    const int nh  = w & 1;

    float acc[8][4];
#pragma unroll
    for (int nt = 0; nt < 8; nt++)
#pragma unroll
        for (int i = 0; i < 4; i++) acc[nt][i] = 0.f;

    {
        const float*  Ah = es_h + (m0 + g) * EPAD + tig;
        const float2* Bb = g_wesB + nh * 8 * 32 + lane;   // global, L2-resident
#pragma unroll
        for (int kt = 0; kt < 4; kt++) {
            const int ko = kt * 8;
            float2 bv[8];
#pragma unroll
            for (int nt = 0; nt < 8; nt++) bv[nt] = __ldg(&Bb[kt * 512 + nt * 32]);
            unsigned a0[4];
            a0[0] = __float_as_uint(Ah[ko]);
            a0[1] = __float_as_uint(Ah[8 * EPAD + ko]);
            a0[2] = __float_as_uint(Ah[ko + 4]);
            a0[3] = __float_as_uint(Ah[8 * EPAD + ko + 4]);
#pragma unroll
            for (int nt = 0; nt < 8; nt++) {
                unsigned b[2] = { __float_as_uint(bv[nt].x), __float_as_uint(bv[nt].y) };
                mma_tf32(acc[nt], a0, b);
            }
        }
    }
    __syncthreads();   // all reads of es_h done -> sout overlay safe

    // ---- epilogue: bias + silu + gate; scalar results -> sout[0..127]
    {
        const int r0 = m0 + g, r1 = m0 + 8 + g;
#pragma unroll
        for (int nt = 0; nt < 8; nt++) {
            int c0 = nh * 64 + nt * 8 + tig * 2;
            float b0 = bes_sh[c0], b1 = bes_sh[c0 + 1];
            float v0 = acc[nt][0] + b0, v1 = acc[nt][1] + b1;
            float v2 = acc[nt][2] + b0, v3 = acc[nt][3] + b1;
            v0 *= sigf(v0); v1 *= sigf(v1); v2 *= sigf(v2); v3 *= sigf(v3);
            *(float2*)(sout + r0 * SPAD + c0) = make_float2(v0, v1);
            *(float2*)(sout + r1 * SPAD + c0) = make_float2(v2, v3);
            if (nh == 0 && nt < 2) {
                gate_sh[r0 * 16 + c0]     = sigf(v0);
                gate_sh[r0 * 16 + c0 + 1] = sigf(v1);
                gate_sh[r1 * 16 + c0]     = sigf(v2);
                gate_sh[r1 * 16 + c0 + 1] = sigf(v3);
            }
        }
    }
    __syncthreads();   // gate_sh + scalar sout visible

    // ---- vector compute: gated values -> sout[128..175] (STS, no atomics)
    if (tid < 192) {
        const int q   = tid >> 4;        // 0..11 -> outputs 4q..4q+3
        const int sub = tid & 15;        // edge stride 16
        float w0[4], w1[4], w2[4], bq[4];
        int   gi[4];
#pragma unroll
        for (int i = 0; i < 4; i++) {
            int o = 4 * q + i;
            w0[i] = wev_sh[o * 3 + 0]; w1[i] = wev_sh[o * 3 + 1];
            w2[i] = wev_sh[o * 3 + 2]; bq[i] = bev_sh[o];
            gi[i] = o / 3;
        }
#pragma unroll
        for (int j = 0; j < 4; j++) {
            int el = sub + 16 * j;
            float e0v = ev_sh[el * 3 + 0], e1v = ev_sh[el * 3 + 1], e2v = ev_sh[el * 3 + 2];
            float4 v; float* vp = (float*)&v;
#pragma unroll
            for (int i = 0; i < 4; i++) {
                float val = fmaf(w0[i], e0v, fmaf(w1[i], e1v, fmaf(w2[i], e2v, bq[i])));
                vp[i] = val * gate_sh[el * 16 + gi[i]];
            }
            *(float4*)(sout + el * SPAD + 128 + 4 * q) = v;
        }
    }
    __syncthreads();

    // ---- unified coalesced scatter: warp w -> 8 edges
#pragma unroll
    for (int j = 0; j < 8; j++) {
        int el = w * 8 + j;
        int d  = dst_sh[el];
        if (d < 0) continue;
        float* ap = g_agg + (size_t)d * 176;
        float4 s = *(const float4*)(sout + el * SPAD + 4 * lane);
        red4(ap + 4 * lane, s);
        if (lane < 12) {
            float4 v = *(const float4*)(sout + el * SPAD + 128 + 4 * lane);
            red4(ap + 128 + 4 * lane, v);
        }
    }
}

// ---------------------------------------------------------------------------
// Node kernel (launch #5; v13 verbatim): persistent, 512 threads, tf32 mma,
// B from L2, single-tf32 A.
// ---------------------------------------------------------------------------
#define XPAD 132
#define NODE_SMEM_FLOATS 17248

__global__ __launch_bounds__(512) void node_kernel(
    const float* __restrict__ node_s, const float* __restrict__ node_v,
    const float* __restrict__ ln_g, const float* __restrict__ ln_b,
    const float* __restrict__ bns, const float* __restrict__ brs,
    const float* __restrict__ bnv, const float* __restrict__ brv,
    float* __restrict__ out, int Nn)
{
    extern __shared__ float smf[];
    float* wVT  = smf;                 // 4608
    float* xh   = wVT + 4608;          // 4224  (x_s tf32 -> wns-result)
    float* sh   = xh + 4224;           // 4224  (raw -> s_n tf32 -> wrs-result)
    float* vn   = sh + 4224;           // 1536
    float* xv   = vn + 1536;           // 1536
    float* gate = xv + 1536;           // 512
    float* lng  = gate + 512;
    float* lnb  = lng + 128;
    float* bnsS = lnb + 128;
    float* brsS = bnsS + 128;
    float* bnvS = brsS + 128;
    float* brvS = bnvS + 48;

    const int tid  = threadIdx.x;
    const int lane = tid & 31;
    const int w    = tid >> 5;
    const int g    = lane >> 2;
    const int tig  = lane & 3;

    for (int i = tid; i < 4608; i += 512) wVT[i] = g_wVT[i];
    if (tid < 128) { lng[tid] = ln_g[tid]; lnb[tid] = ln_b[tid];
                     bnsS[tid] = bns[tid]; brsS[tid] = brs[tid]; }
    if (tid < 48)  { bnvS[tid] = bnv[tid]; brvS[tid] = brv[tid]; }

    const int mstrip = w >> 3;
    const int nstrip = w & 7;
    const int m0     = mstrip * 16;
    const bool wnsP  = (nstrip < 4);
    const float2* Bb = g_wB + (nstrip * 4) * 32 + lane;   // global, L2-resident

    const int ntiles = (Nn + 31) / 32;
    for (int tile = blockIdx.x; tile < ntiles; tile += gridDim.x) {
        const int n0t = tile * 32;
        const int nN  = min(32, Nn - n0t);
        __syncthreads();

        for (int i = tid; i < 4096; i += 512) {
            int r = i >> 7, c = i & 127;
            sh[r * XPAD + c] = (i < nN * 128) ? node_s[(size_t)n0t * 128 + i] : 0.f;
        }
        for (int i = tid; i < 1536; i += 512)
            vn[i] = (i < nN * 48) ? node_v[(size_t)n0t * 48 + i] : 0.f;
        __syncthreads();

        for (int q = 0; q < 2; q++) {
            int r = w * 2 + q;
            int n = n0t + r;
            const float* row = sh + r * XPAD;
            float a = row[lane] + row[lane + 32] + row[lane + 64] + row[lane + 96];
#pragma unroll
            for (int o = 16; o; o >>= 1) a += __shfl_xor_sync(0xffffffffu, a, o);
            float mu = a * (1.f / 128.f);
            float d0 = row[lane] - mu, d1 = row[lane + 32] - mu;
            float d2 = row[lane + 64] - mu, d3 = row[lane + 96] - mu;
            float vv = d0 * d0 + d1 * d1 + d2 * d2 + d3 * d3;
#pragma unroll
            for (int o = 16; o; o >>= 1) vv += __shfl_xor_sync(0xffffffffu, vv, o);
            float rs = rsqrtf(vv * (1.f / 128.f) + 1e-5f);

            const float* vrow = vn + r * 48;
            float x0 = vrow[lane];
            float x1 = (lane < 16) ? vrow[32 + lane] : 0.f;
            float sq = x0 * x0 + x1 * x1;
#pragma unroll
            for (int o = 16; o; o >>= 1) sq += __shfl_xor_sync(0xffffffffu, sq, o);
            float vr = rsqrtf(sq * (1.f / 16.f) + 1e-8f);

            float invden = 0.f;
            const float* aggr = g_agg + (size_t)n * 176;
            if (r < nN) invden = 1.f / fmaxf(g_cnt[n], 1.f);

#pragma unroll
            for (int jj = 0; jj < 4; jj++) {
                int c = lane + 32 * jj;
                float x = (row[c] - mu) * rs * lng[c] + lnb[c];
                float xa = x;
                if (r < nN) xa = x + aggr[c] * invden;
                sh[r * XPAD + c] = tf32f(x);       // s_n (tf32, wrs path)
                xh[r * XPAD + c] = tf32f(xa);      // x_s (tf32, wns path)
            }
            {
                float x = x0 * vr;
                float xa = x;
                if (r < nN) xa = x + aggr[128 + lane] * invden;
                vn[r * 48 + lane] = x;
                xv[r * 48 + lane] = xa;
                if (lane < 16) {
                    float y = x1 * vr;
                    float ya = y;
                    if (r < nN) ya = y + aggr[128 + 32 + lane] * invden;
                    vn[r * 48 + 32 + lane] = y;
                    xv[r * 48 + 32 + lane] = ya;
                }
            }
        }
        __syncthreads();

        float acc[4][4];
#pragma unroll
        for (int nt = 0; nt < 4; nt++)
#pragma unroll
            for (int i = 0; i < 4; i++) acc[nt][i] = 0.f;

        {
            const float* A = wnsP ? xh : sh;
            const int arow = (m0 + g) * XPAD + tig;
#pragma unroll 4
            for (int kt = 0; kt < 16; kt++) {
                const int ko = kt * 8;
                float2 bv[4];
#pragma unroll
                for (int nt = 0; nt < 4; nt++) bv[nt] = __ldg(&Bb[kt * 1024 + nt * 32]);
                unsigned a0[4];
                a0[0] = __float_as_uint(A[arow + ko]);
                a0[1] = __float_as_uint(A[arow + 8 * XPAD + ko]);
                a0[2] = __float_as_uint(A[arow + ko + 4]);
                a0[3] = __float_as_uint(A[arow + 8 * XPAD + ko + 4]);
#pragma unroll
                for (int nt = 0; nt < 4; nt++) {
                    unsigned b[2] = { __float_as_uint(bv[nt].x), __float_as_uint(bv[nt].y) };
                    mma_tf32(acc[nt], a0, b);
                }
            }
        }
        __syncthreads();

        {
            const int r0 = m0 + g, r1 = m0 + 8 + g;
#pragma unroll
            for (int nt = 0; nt < 4; nt++) {
                int o = nstrip * 32 + nt * 8 + tig * 2;
                if (wnsP) {
                    float b0v = bnsS[o], b1v = bnsS[o + 1];
                    float v0 = acc[nt][0] + b0v, v1 = acc[nt][1] + b1v;
                    float v2 = acc[nt][2] + b0v, v3 = acc[nt][3] + b1v;
                    v0 *= sigf(v0); v1 *= sigf(v1); v2 *= sigf(v2); v3 *= sigf(v3);
                    xh[r0 * XPAD + o]     = v0;
                    xh[r0 * XPAD + o + 1] = v1;
                    xh[r1 * XPAD + o]     = v2;
                    xh[r1 * XPAD + o + 1] = v3;
                    if (o < 16) {
                        gate[r0 * 16 + o]     = sigf(v0);
                        gate[r0 * 16 + o + 1] = sigf(v1);
                        gate[r1 * 16 + o]     = sigf(v2);
                        gate[r1 * 16 + o + 1] = sigf(v3);
                    }
                } else {
                    int oc = o - 128;
                    float b0v = brsS[oc], b1v = brsS[oc + 1];
                    sh[r0 * XPAD + oc]     = acc[nt][0] + b0v;
                    sh[r0 * XPAD + oc + 1] = acc[nt][1] + b1v;
                    sh[r1 * XPAD + oc]     = acc[nt][2] + b0v;
                    sh[r1 * XPAD + oc + 1] = acc[nt][3] + b1v;
                }
            }
        }
        __syncthreads();

        for (int i = tid; i < nN * 128; i += 512) {
            int r = i >> 7, c = i & 127;
            out[(size_t)n0t * 128 + i] = xh[r * XPAD + c] + sh[r * XPAD + c];
        }

        for (int p = tid; p < nN * 48; p += 512) {
            int r = p / 48, o = p % 48;
            const float* xvr = xv + r * 48;
            const float* vnr = vn + r * 48;
            float a = 0.f, bq = 0.f;
#pragma unroll 4
            for (int k = 0; k < 48; k++) {
                a  = fmaf(xvr[k], wVT[k * 96 + o],      a);
                bq = fmaf(vnr[k], wVT[k * 96 + 48 + o], bq);
            }
            float val = (a + bnvS[o]) * gate[r * 16 + o / 3] + bq + brvS[o];
            out[(size_t)Nn * 128 + (size_t)n0t * 48 + p] = val;
        }
    }
}

// ---------------------------------------------------------------------------
extern "C" void kernel_launch(void* const* d_in, const int* in_sizes, int n_in,
                              void* d_out, int out_size)
{
    const float* node_s = (const float*)d_in[0];
    const float* node_v = (const float*)d_in[1];
    const int*   ei     = (const int*)  d_in[2];
    const float* edge_s = (const float*)d_in[3];
    const float* edge_v = (const float*)d_in[4];
    const float* ln_g   = (const float*)d_in[5];
    const float* ln_b   = (const float*)d_in[6];
    const float* wes    = (const float*)d_in[7];
    const float* bes    = (const float*)d_in[8];
    const float* wev    = (const float*)d_in[9];
    const float* bev    = (const float*)d_in[10];
    const float* wns    = (const float*)d_in[11];
    const float* bns    = (const float*)d_in[12];
    const float* wnv    = (const float*)d_in[13];
    const float* bnv    = (const float*)d_in[14];
    const float* wrs    = (const float*)d_in[15];
    const float* brs    = (const float*)d_in[16];
    const float* wrv    = (const float*)d_in[17];
    const float* brv    = (const float*)d_in[18];

    const int N = in_sizes[0] / 128;
    const int E = in_sizes[3] / 32;

    cudaFuncSetAttribute(node_kernel, cudaFuncAttributeMaxDynamicSharedMemorySize,
                         NODE_SMEM_FLOATS * sizeof(float));

    prep_kernel<<<64, 256>>>(wes, wns, wrs, wnv, wrv);                  // #1
    zero_agg_kernel<<<(N * 44 + 255) / 256, 256>>>(N);                  // #2
    zero_cnt_kernel<<<(N + 255) / 256, 256>>>(N);                       // #3
    edge_kernel<<<(E + TE - 1) / TE, 256>>>(edge_s, edge_v, ei,         // #4 (ncu)
                                            bes, wev, bev, E);
    node_kernel<<<304, 512, NODE_SMEM_FLOATS * sizeof(float)>>>(        // #5
        node_s, node_v, ln_g, ln_b, bns, brs, bnv, brv, (float*)d_out, N);
}

// round 16
// speedup vs baseline: 1.1196x; 1.1196x over previous
#include <cuda_runtime.h>

// ---------------------------------------------------------------------------
// MultiGVPConvLayer fused, v15: v13 structure (best), plus:
//   - sigf via __fdividef (fast rcp) everywhere  (~6 instr saved per sigf)
//   - edge __launch_bounds__(256, 5) -> occ 46% -> ~60%
//   Launch order: prep, zero_agg, zero_cnt, edge (#4 -> ncu), node
//   Output: concat( out_s [N,128], out_v [N,48] ) float32
// ---------------------------------------------------------------------------

#define NMAX 50000
#define TE 64
#define EPAD 36
#define SPAD 132

__device__ float  g_agg[(size_t)NMAX * 176];  // per-node [128 s | 48 v] sums
__device__ float  g_cnt[NMAX];                // in-degree counts
__device__ float2 g_wesB[2048];               // edge B-frags [kt4][ntg16][lane32] tf32
__device__ float2 g_wB[16384];                // node B-frags [kt16][ntg32][lane32] tf32
__device__ float  g_wVT[48 * 96];             // [k][ wnv_out(48) | wrv_out(48) ]

__device__ __forceinline__ float sigf(float x) {
    return __fdividef(1.f, 1.f + __expf(-x));
}

__device__ __forceinline__ void red4(float* p, float4 v) {
    asm volatile("red.global.add.v4.f32 [%0], {%1,%2,%3,%4};"
                 :: "l"(p), "f"(v.x), "f"(v.y), "f"(v.z), "f"(v.w) : "memory");
}

__device__ __forceinline__ unsigned tf32u(float f) {
    unsigned u;
    asm("cvt.rna.tf32.f32 %0, %1;" : "=r"(u) : "f"(f));
    return u;
}
__device__ __forceinline__ float tf32f(float f) { return __uint_as_float(tf32u(f)); }

__device__ __forceinline__ void mma_tf32(float* d, const unsigned* a, const unsigned* b) {
    asm volatile(
        "mma.sync.aligned.m16n8k8.row.col.f32.tf32.tf32.f32 "
        "{%0,%1,%2,%3}, {%4,%5,%6,%7}, {%8,%9}, {%0,%1,%2,%3};"
        : "+f"(d[0]), "+f"(d[1]), "+f"(d[2]), "+f"(d[3])
        : "r"(a[0]), "r"(a[1]), "r"(a[2]), "r"(a[3]), "r"(b[0]), "r"(b[1]));
}

// ---------------------------------------------------------------------------
__global__ void prep_kernel(const float* __restrict__ wes,     // launch #1
                            const float* __restrict__ wns, const float* __restrict__ wrs,
                            const float* __restrict__ wnv, const float* __restrict__ wrv)
{
    int t = blockIdx.x * 256 + threadIdx.x;
    if (t < 2048) {             // edge B frags
        int lane = t & 31, ntg = (t >> 5) & 15, kt = t >> 9;
        int g = lane >> 2, tig = lane & 3;
        int k = kt * 8 + tig;
        int n = ntg * 8 + g;
        g_wesB[t] = make_float2(tf32f(wes[n * 32 + k]), tf32f(wes[n * 32 + k + 4]));
    }
    if (t < 16384) {            // node B frags
        int lane = t & 31, ntg = (t >> 5) & 31, kt = t >> 10;
        int g = lane >> 2, tig = lane & 3;
        int k = kt * 8 + tig;
        int n = ntg * 8 + g;
        const float* srow = (n < 128) ? (wns + n * 128) : (wrs + (n - 128) * 128);
        g_wB[t] = make_float2(tf32f(srow[k]), tf32f(srow[k + 4]));
    }
    if (t < 48 * 48) { int o = t / 48, k = t % 48; g_wVT[k * 96 + o] = wnv[t];
                                                   g_wVT[k * 96 + 48 + o] = wrv[t]; }
}

__global__ void zero_agg_kernel(int Nn)                        // launch #2
{
    size_t t = (size_t)blockIdx.x * 256 + threadIdx.x;
    if (t < (size_t)Nn * 44) ((float4*)g_agg)[t] = make_float4(0.f, 0.f, 0.f, 0.f);
}
__global__ void zero_cnt_kernel(int Nn)                        // launch #3
{
    int t = blockIdx.x * 256 + threadIdx.x;
    if (t < Nn) g_cnt[t] = 0.f;
}

// ---------------------------------------------------------------------------
// Edge kernel (launch #4 -> ncu). 64 edges / 256 threads; v13 structure,
// B fragments via __ldg from L2; minBlocksPerMultiprocessor = 5.
// ---------------------------------------------------------------------------
__global__ __launch_bounds__(256, 5) void edge_kernel(
    const float* __restrict__ edge_s, const float* __restrict__ edge_v,
    const int* __restrict__ edge_index,
    const float* __restrict__ bes, const float* __restrict__ wev,
    const float* __restrict__ bev, int E)
{
    __shared__ char  uni[33792];         // es_h [64][36] overlaid by sout [64][132]
    __shared__ float ev_sh[TE * 3];
    __shared__ int   dst_sh[TE];
    __shared__ float gate_sh[TE * 16];
    __shared__ float bes_sh[128];
    __shared__ float wev_sh[144];
    __shared__ float bev_sh[48];

    float* es_h = (float*)uni;                         // [64][36] during mma
    float* sout = (float*)uni;                         // [64][132] after mma

    const int tid  = threadIdx.x;
    const int lane = tid & 31;
    const int w    = tid >> 5;
    const int e0   = blockIdx.x * TE;
    const int nE   = min(TE, E - e0);

    // ---- stage edge_s (tf32, float4) + params (no B copy)
    {
        const float4* s4 = (const float4*)(edge_s + (size_t)e0 * 32);
        for (int i = tid; i < TE * 8; i += 256) {
            int e = i >> 3, c = (i & 7) * 4;
            float4 v = (e < nE) ? s4[i] : make_float4(0.f, 0.f, 0.f, 0.f);
            float4 h;
            h.x = tf32f(v.x); h.y = tf32f(v.y); h.z = tf32f(v.z); h.w = tf32f(v.w);
            *(float4*)(es_h + e * EPAD + c) = h;
        }
    }
    if (tid < TE * 3) { int e = tid / 3; ev_sh[tid] = (e < nE) ? edge_v[(size_t)e0 * 3 + tid] : 0.f; }
    if (tid < TE) {
        int d = -1;
        if (tid < nE) { d = edge_index[E + e0 + tid]; atomicAdd(&g_cnt[d], 1.f); }
        dst_sh[tid] = d;
    }
    if (tid < 128) bes_sh[tid] = bes[tid];
    if (tid < 144) wev_sh[tid] = wev[tid];
    if (tid < 48)  bev_sh[tid] = bev[tid];
    __syncthreads();

    // ---- mma mainloop (A single tf32; B via __ldg from L2)
    const int g   = lane >> 2;
    const int tig = lane & 3;
    const int m0  = (w >> 1) * 16;
    const int nh  = w & 1;

    float acc[8][4];
#pragma unroll
    for (int nt = 0; nt < 8; nt++)
#pragma unroll
        for (int i = 0; i < 4; i++) acc[nt][i] = 0.f;

    {
        const float*  Ah = es_h + (m0 + g) * EPAD + tig;
        const float2* Bb = g_wesB + nh * 8 * 32 + lane;   // global, L2-resident
#pragma unroll
        for (int kt = 0; kt < 4; kt++) {
            const int ko = kt * 8;
            unsigned a0[4];
            a0[0] = __float_as_uint(Ah[ko]);
            a0[1] = __float_as_uint(Ah[8 * EPAD + ko]);
            a0[2] = __float_as_uint(Ah[ko + 4]);
            a0[3] = __float_as_uint(Ah[8 * EPAD + ko + 4]);
            // B in two halves (reduces live registers)
#pragma unroll
            for (int half = 0; half < 2; half++) {
                float2 bv[4];
#pragma unroll
                for (int q = 0; q < 4; q++)
                    bv[q] = __ldg(&Bb[kt * 512 + (half * 4 + q) * 32]);
#pragma unroll
                for (int q = 0; q < 4; q++) {
                    unsigned b[2] = { __float_as_uint(bv[q].x), __float_as_uint(bv[q].y) };
                    mma_tf32(acc[half * 4 + q], a0, b);
                }
            }
        }
    }
    __syncthreads();   // all reads of es_h done -> sout overlay safe

    // ---- epilogue: bias + silu + gate; stage to sout (coalescing buffer)
    {
        const int r0 = m0 + g, r1 = m0 + 8 + g;
#pragma unroll
        for (int nt = 0; nt < 8; nt++) {
            int c0 = nh * 64 + nt * 8 + tig * 2;
            float b0 = bes_sh[c0], b1 = bes_sh[c0 + 1];
            float v0 = acc[nt][0] + b0, v1 = acc[nt][1] + b1;
            float v2 = acc[nt][2] + b0, v3 = acc[nt][3] + b1;
            v0 *= sigf(v0); v1 *= sigf(v1); v2 *= sigf(v2); v3 *= sigf(v3);
            *(float2*)(sout + r0 * SPAD + c0) = make_float2(v0, v1);
            *(float2*)(sout + r1 * SPAD + c0) = make_float2(v2, v3);
            if (nh == 0 && nt < 2) {
                gate_sh[r0 * 16 + c0]     = sigf(v0);
                gate_sh[r0 * 16 + c0 + 1] = sigf(v1);
                gate_sh[r1 * 16 + c0]     = sigf(v2);
                gate_sh[r1 * 16 + c0 + 1] = sigf(v3);
            }
        }
    }
    __syncthreads();

    // ---- scalar scatter: warp w -> 8 edges, lane = 4 outputs (coalesced red4)
#pragma unroll
    for (int j = 0; j < 8; j++) {
        int el = w * 8 + j;
        if (el >= nE) break;
        float4 s = *(const float4*)(sout + el * SPAD + 4 * lane);
        red4(g_agg + (size_t)dst_sh[el] * 176 + 4 * lane, s);
    }

    // ---- vector part: 192 threads; thread = (q, sub) -> quad q over 4 edges
    if (tid < 192) {
        const int q   = tid >> 4;
        const int sub = tid & 15;
        float w0[4], w1[4], w2[4], bq[4];
        int   gi[4];
#pragma unroll
        for (int i = 0; i < 4; i++) {
            int o = 4 * q + i;
            w0[i] = wev_sh[o * 3 + 0]; w1[i] = wev_sh[o * 3 + 1];
            w2[i] = wev_sh[o * 3 + 2]; bq[i] = bev_sh[o];
            gi[i] = o / 3;
        }
#pragma unroll
        for (int j = 0; j < 4; j++) {
            int el = sub + 16 * j;
            if (el >= nE) continue;
            float e0v = ev_sh[el * 3 + 0], e1v = ev_sh[el * 3 + 1], e2v = ev_sh[el * 3 + 2];
            float4 v; float* vp = (float*)&v;
#pragma unroll
            for (int i = 0; i < 4; i++) {
                float val = fmaf(w0[i], e0v, fmaf(w1[i], e1v, fmaf(w2[i], e2v, bq[i])));
                vp[i] = val * gate_sh[el * 16 + gi[i]];
            }
            red4(g_agg + (size_t)dst_sh[el] * 176 + 128 + 4 * q, v);
        }
    }
}

// ---------------------------------------------------------------------------
// Node kernel (launch #5): persistent, 512 threads, tf32 mma, B from L2,
// single-tf32 A (v13 verbatim except sigf).
// ---------------------------------------------------------------------------
#define XPAD 132
#define NODE_SMEM_FLOATS 17248

__global__ __launch_bounds__(512) void node_kernel(
    const float* __restrict__ node_s, const float* __restrict__ node_v,
    const float* __restrict__ ln_g, const float* __restrict__ ln_b,
    const float* __restrict__ bns, const float* __restrict__ brs,
    const float* __restrict__ bnv, const float* __restrict__ brv,
    float* __restrict__ out, int Nn)
{
    extern __shared__ float smf[];
    float* wVT  = smf;                 // 4608
    float* xh   = wVT + 4608;          // 4224  (x_s tf32 -> wns-result)
    float* sh   = xh + 4224;           // 4224  (raw -> s_n tf32 -> wrs-result)
    float* vn   = sh + 4224;           // 1536
    float* xv   = vn + 1536;           // 1536
    float* gate = xv + 1536;           // 512
    float* lng  = gate + 512;
    float* lnb  = lng + 128;
    float* bnsS = lnb + 128;
    float* brsS = bnsS + 128;
    float* bnvS = brsS + 128;
    float* brvS = bnvS + 48;

    const int tid  = threadIdx.x;
    const int lane = tid & 31;
    const int w    = tid >> 5;
    const int g    = lane >> 2;
    const int tig  = lane & 3;

    for (int i = tid; i < 4608; i += 512) wVT[i] = g_wVT[i];
    if (tid < 128) { lng[tid] = ln_g[tid]; lnb[tid] = ln_b[tid];
                     bnsS[tid] = bns[tid]; brsS[tid] = brs[tid]; }
    if (tid < 48)  { bnvS[tid] = bnv[tid]; brvS[tid] = brv[tid]; }

    const int mstrip = w >> 3;
    const int nstrip = w & 7;
    const int m0     = mstrip * 16;
    const bool wnsP  = (nstrip < 4);
    const float2* Bb = g_wB + (nstrip * 4) * 32 + lane;   // global, L2-resident

    const int ntiles = (Nn + 31) / 32;
    for (int tile = blockIdx.x; tile < ntiles; tile += gridDim.x) {
        const int n0t = tile * 32;
        const int nN  = min(32, Nn - n0t);
        __syncthreads();

        for (int i = tid; i < 4096; i += 512) {
            int r = i >> 7, c = i & 127;
            sh[r * XPAD + c] = (i < nN * 128) ? node_s[(size_t)n0t * 128 + i] : 0.f;
        }
        for (int i = tid; i < 1536; i += 512)
            vn[i] = (i < nN * 48) ? node_v[(size_t)n0t * 48 + i] : 0.f;
        __syncthreads();

        for (int q = 0; q < 2; q++) {
            int r = w * 2 + q;
            int n = n0t + r;
            const float* row = sh + r * XPAD;
            float a = row[lane] + row[lane + 32] + row[lane + 64] + row[lane + 96];
#pragma unroll
            for (int o = 16; o; o >>= 1) a += __shfl_xor_sync(0xffffffffu, a, o);
            float mu = a * (1.f / 128.f);
            float d0 = row[lane] - mu, d1 = row[lane + 32] - mu;
            float d2 = row[lane + 64] - mu, d3 = row[lane + 96] - mu;
            float vv = d0 * d0 + d1 * d1 + d2 * d2 + d3 * d3;
#pragma unroll
            for (int o = 16; o; o >>= 1) vv += __shfl_xor_sync(0xffffffffu, vv, o);
            float rs = rsqrtf(vv * (1.f / 128.f) + 1e-5f);

            const float* vrow = vn + r * 48;
            float x0 = vrow[lane];
            float x1 = (lane < 16) ? vrow[32 + lane] : 0.f;
            float sq = x0 * x0 + x1 * x1;
#pragma unroll
            for (int o = 16; o; o >>= 1) sq += __shfl_xor_sync(0xffffffffu, sq, o);
            float vr = rsqrtf(sq * (1.f / 16.f) + 1e-8f);

            float invden = 0.f;
            const float* aggr = g_agg + (size_t)n * 176;
            if (r < nN) invden = __fdividef(1.f, fmaxf(g_cnt[n], 1.f));

#pragma unroll
            for (int jj = 0; jj < 4; jj++) {
                int c = lane + 32 * jj;
                float x = (row[c] - mu) * rs * lng[c] + lnb[c];
                float xa = x;
                if (r < nN) xa = x + aggr[c] * invden;
                sh[r * XPAD + c] = tf32f(x);       // s_n (tf32, wrs path)
                xh[r * XPAD + c] = tf32f(xa);      // x_s (tf32, wns path)
            }
            {
                float x = x0 * vr;
                float xa = x;
                if (r < nN) xa = x + aggr[128 + lane] * invden;
                vn[r * 48 + lane] = x;
                xv[r * 48 + lane] = xa;
                if (lane < 16) {
                    float y = x1 * vr;
                    float ya = y;
                    if (r < nN) ya = y + aggr[128 + 32 + lane] * invden;
                    vn[r * 48 + 32 + lane] = y;
                    xv[r * 48 + 32 + lane] = ya;
                }
            }
        }
        __syncthreads();

        float acc[4][4];
#pragma unroll
        for (int nt = 0; nt < 4; nt++)
#pragma unroll
            for (int i = 0; i < 4; i++) acc[nt][i] = 0.f;

        {
            const float* A = wnsP ? xh : sh;
            const int arow = (m0 + g) * XPAD + tig;
#pragma unroll 4
            for (int kt = 0; kt < 16; kt++) {
                const int ko = kt * 8;
                float2 bv[4];
#pragma unroll
                for (int nt = 0; nt < 4; nt++) bv[nt] = __ldg(&Bb[kt * 1024 + nt * 32]);
                unsigned a0[4];
                a0[0] = __float_as_uint(A[arow + ko]);
                a0[1] = __float_as_uint(A[arow + 8 * XPAD + ko]);
                a0[2] = __float_as_uint(A[arow + ko + 4]);
                a0[3] = __float_as_uint(A[arow + 8 * XPAD + ko + 4]);
#pragma unroll
                for (int nt = 0; nt < 4; nt++) {
                    unsigned b[2] = { __float_as_uint(bv[nt].x), __float_as_uint(bv[nt].y) };
                    mma_tf32(acc[nt], a0, b);
                }
            }
        }
        __syncthreads();

        {
            const int r0 = m0 + g, r1 = m0 + 8 + g;
#pragma unroll
            for (int nt = 0; nt < 4; nt++) {
                int o = nstrip * 32 + nt * 8 + tig * 2;
                if (wnsP) {
                    float b0v = bnsS[o], b1v = bnsS[o + 1];
                    float v0 = acc[nt][0] + b0v, v1 = acc[nt][1] + b1v;
                    float v2 = acc[nt][2] + b0v, v3 = acc[nt][3] + b1v;
                    v0 *= sigf(v0); v1 *= sigf(v1); v2 *= sigf(v2); v3 *= sigf(v3);
                    xh[r0 * XPAD + o]     = v0;
                    xh[r0 * XPAD + o + 1] = v1;
                    xh[r1 * XPAD + o]     = v2;
                    xh[r1 * XPAD + o + 1] = v3;
                    if (o < 16) {
                        gate[r0 * 16 + o]     = sigf(v0);
                        gate[r0 * 16 + o + 1] = sigf(v1);
                        gate[r1 * 16 + o]     = sigf(v2);
                        gate[r1 * 16 + o + 1] = sigf(v3);
                    }
                } else {
                    int oc = o - 128;
                    float b0v = brsS[oc], b1v = brsS[oc + 1];
                    sh[r0 * XPAD + oc]     = acc[nt][0] + b0v;
                    sh[r0 * XPAD + oc + 1] = acc[nt][1] + b1v;
                    sh[r1 * XPAD + oc]     = acc[nt][2] + b0v;
                    sh[r1 * XPAD + oc + 1] = acc[nt][3] + b1v;
                }
            }
        }
        __syncthreads();

        for (int i = tid; i < nN * 128; i += 512) {
            int r = i >> 7, c = i & 127;
            out[(size_t)n0t * 128 + i] = xh[r * XPAD + c] + sh[r * XPAD + c];
        }

        for (int p = tid; p < nN * 48; p += 512) {
            int r = p / 48, o = p % 48;
            const float* xvr = xv + r * 48;
            const float* vnr = vn + r * 48;
            float a = 0.f, bq = 0.f;
#pragma unroll 4
            for (int k = 0; k < 48; k++) {
                a  = fmaf(xvr[k], wVT[k * 96 + o],      a);
                bq = fmaf(vnr[k], wVT[k * 96 + 48 + o], bq);
            }
            float val = (a + bnvS[o]) * gate[r * 16 + o / 3] + bq + brvS[o];
            out[(size_t)Nn * 128 + (size_t)n0t * 48 + p] = val;
        }
    }
}

// ---------------------------------------------------------------------------
extern "C" void kernel_launch(void* const* d_in, const int* in_sizes, int n_in,
                              void* d_out, int out_size)
{
    const float* node_s = (const float*)d_in[0];
    const float* node_v = (const float*)d_in[1];
    const int*   ei     = (const int*)  d_in[2];
    const float* edge_s = (const float*)d_in[3];
    const float* edge_v = (const float*)d_in[4];
    const float* ln_g   = (const float*)d_in[5];
    const float* ln_b   = (const float*)d_in[6];
    const float* wes    = (const float*)d_in[7];
    const float* bes    = (const float*)d_in[8];
    const float* wev    = (const float*)d_in[9];
    const float* bev    = (const float*)d_in[10];
    const float* wns    = (const float*)d_in[11];
    const float* bns    = (const float*)d_in[12];
    const float* wnv    = (const float*)d_in[13];
    const float* bnv    = (const float*)d_in[14];
    const float* wrs    = (const float*)d_in[15];
    const float* brs    = (const float*)d_in[16];
    const float* wrv    = (const float*)d_in[17];
    const float* brv    = (const float*)d_in[18];

    const int N = in_sizes[0] / 128;
    const int E = in_sizes[3] / 32;

    cudaFuncSetAttribute(node_kernel, cudaFuncAttributeMaxDynamicSharedMemorySize,
                         NODE_SMEM_FLOATS * sizeof(float));

    prep_kernel<<<64, 256>>>(wes, wns, wrs, wnv, wrv);                  // #1
    zero_agg_kernel<<<(N * 44 + 255) / 256, 256>>>(N);                  // #2
    zero_cnt_kernel<<<(N + 255) / 256, 256>>>(N);                       // #3
    edge_kernel<<<(E + TE - 1) / TE, 256>>>(edge_s, edge_v, ei,         // #4 (ncu)
                                            bes, wev, bev, E);
    node_kernel<<<304, 512, NODE_SMEM_FLOATS * sizeof(float)>>>(        // #5
        node_s, node_v, ln_g, ln_b, bns, brs, bnv, brv, (float*)d_out, N);
}

// round 17
// speedup vs baseline: 1.1583x; 1.0346x over previous
#include <cuda_runtime.h>

// ---------------------------------------------------------------------------
// MultiGVPConvLayer fused, v16: v15 + node __launch_bounds__(512,3) (regs
// forced <=41 -> 3 blocks/SM) + grid 456; cnt-zero folded into prep.
//   Launch order: prep(+cnt), zero_agg, edge, node (#4 -> ncu)
//   Output: concat( out_s [N,128], out_v [N,48] ) float32
// ---------------------------------------------------------------------------

#define NMAX 50000
#define TE 64
#define EPAD 36
#define SPAD 132

__device__ float  g_agg[(size_t)NMAX * 176];  // per-node [128 s | 48 v] sums
__device__ float  g_cnt[NMAX];                // in-degree counts
__device__ float2 g_wesB[2048];               // edge B-frags [kt4][ntg16][lane32] tf32
__device__ float2 g_wB[16384];                // node B-frags [kt16][ntg32][lane32] tf32
__device__ float  g_wVT[48 * 96];             // [k][ wnv_out(48) | wrv_out(48) ]

__device__ __forceinline__ float sigf(float x) {
    return __fdividef(1.f, 1.f + __expf(-x));
}

__device__ __forceinline__ void red4(float* p, float4 v) {
    asm volatile("red.global.add.v4.f32 [%0], {%1,%2,%3,%4};"
                 :: "l"(p), "f"(v.x), "f"(v.y), "f"(v.z), "f"(v.w) : "memory");
}

__device__ __forceinline__ unsigned tf32u(float f) {
    unsigned u;
    asm("cvt.rna.tf32.f32 %0, %1;" : "=r"(u) : "f"(f));
    return u;
}
__device__ __forceinline__ float tf32f(float f) { return __uint_as_float(tf32u(f)); }

__device__ __forceinline__ void mma_tf32(float* d, const unsigned* a, const unsigned* b) {
    asm volatile(
        "mma.sync.aligned.m16n8k8.row.col.f32.tf32.tf32.f32 "
        "{%0,%1,%2,%3}, {%4,%5,%6,%7}, {%8,%9}, {%0,%1,%2,%3};"
        : "+f"(d[0]), "+f"(d[1]), "+f"(d[2]), "+f"(d[3])
        : "r"(a[0]), "r"(a[1]), "r"(a[2]), "r"(a[3]), "r"(b[0]), "r"(b[1]));
}

// ---------------------------------------------------------------------------
__global__ void prep_kernel(const float* __restrict__ wes,     // launch #1
                            const float* __restrict__ wns, const float* __restrict__ wrs,
                            const float* __restrict__ wnv, const float* __restrict__ wrv,
                            int Nn)
{
    int t = blockIdx.x * 256 + threadIdx.x;
    if (t < 2048) {             // edge B frags
        int lane = t & 31, ntg = (t >> 5) & 15, kt = t >> 9;
        int g = lane >> 2, tig = lane & 3;
        int k = kt * 8 + tig;
        int n = ntg * 8 + g;
        g_wesB[t] = make_float2(tf32f(wes[n * 32 + k]), tf32f(wes[n * 32 + k + 4]));
    }
    if (t < 16384) {            // node B frags
        int lane = t & 31, ntg = (t >> 5) & 31, kt = t >> 10;
        int g = lane >> 2, tig = lane & 3;
        int k = kt * 8 + tig;
        int n = ntg * 8 + g;
        const float* srow = (n < 128) ? (wns + n * 128) : (wrs + (n - 128) * 128);
        g_wB[t] = make_float2(tf32f(srow[k]), tf32f(srow[k + 4]));
    }
    if (t < 48 * 48) { int o = t / 48, k = t % 48; g_wVT[k * 96 + o] = wnv[t];
                                                   g_wVT[k * 96 + 48 + o] = wrv[t]; }
    if (t < Nn) g_cnt[t] = 0.f;
}

__global__ void zero_agg_kernel(int Nn)                        // launch #2
{
    size_t t = (size_t)blockIdx.x * 256 + threadIdx.x;
    if (t < (size_t)Nn * 44) ((float4*)g_agg)[t] = make_float4(0.f, 0.f, 0.f, 0.f);
}

// ---------------------------------------------------------------------------
// Edge kernel (launch #3; v15 verbatim). 64 edges / 256 threads, 5 blk/SM.
// ---------------------------------------------------------------------------
__global__ __launch_bounds__(256, 5) void edge_kernel(
    const float* __restrict__ edge_s, const float* __restrict__ edge_v,
    const int* __restrict__ edge_index,
    const float* __restrict__ bes, const float* __restrict__ wev,
    const float* __restrict__ bev, int E)
{
    __shared__ char  uni[33792];         // es_h [64][36] overlaid by sout [64][132]
    __shared__ float ev_sh[TE * 3];
    __shared__ int   dst_sh[TE];
    __shared__ float gate_sh[TE * 16];
    __shared__ float bes_sh[128];
    __shared__ float wev_sh[144];
    __shared__ float bev_sh[48];

    float* es_h = (float*)uni;                         // [64][36] during mma
    float* sout = (float*)uni;                         // [64][132] after mma

    const int tid  = threadIdx.x;
    const int lane = tid & 31;
    const int w    = tid >> 5;
    const int e0   = blockIdx.x * TE;
    const int nE   = min(TE, E - e0);

    {
        const float4* s4 = (const float4*)(edge_s + (size_t)e0 * 32);
        for (int i = tid; i < TE * 8; i += 256) {
            int e = i >> 3, c = (i & 7) * 4;
            float4 v = (e < nE) ? s4[i] : make_float4(0.f, 0.f, 0.f, 0.f);
            float4 h;
            h.x = tf32f(v.x); h.y = tf32f(v.y); h.z = tf32f(v.z); h.w = tf32f(v.w);
            *(float4*)(es_h + e * EPAD + c) = h;
        }
    }
    if (tid < TE * 3) { int e = tid / 3; ev_sh[tid] = (e < nE) ? edge_v[(size_t)e0 * 3 + tid] : 0.f; }
    if (tid < TE) {
        int d = -1;
        if (tid < nE) { d = edge_index[E + e0 + tid]; atomicAdd(&g_cnt[d], 1.f); }
        dst_sh[tid] = d;
    }
    if (tid < 128) bes_sh[tid] = bes[tid];
    if (tid < 144) wev_sh[tid] = wev[tid];
    if (tid < 48)  bev_sh[tid] = bev[tid];
    __syncthreads();

    const int g   = lane >> 2;
    const int tig = lane & 3;
    const int m0  = (w >> 1) * 16;
    const int nh  = w & 1;

    float acc[8][4];
#pragma unroll
    for (int nt = 0; nt < 8; nt++)
#pragma unroll
        for (int i = 0; i < 4; i++) acc[nt][i] = 0.f;

    {
        const float*  Ah = es_h + (m0 + g) * EPAD + tig;
        const float2* Bb = g_wesB + nh * 8 * 32 + lane;   // global, L2-resident
#pragma unroll
        for (int kt = 0; kt < 4; kt++) {
            const int ko = kt * 8;
            unsigned a0[4];
            a0[0] = __float_as_uint(Ah[ko]);
            a0[1] = __float_as_uint(Ah[8 * EPAD + ko]);
            a0[2] = __float_as_uint(Ah[ko + 4]);
            a0[3] = __float_as_uint(Ah[8 * EPAD + ko + 4]);
#pragma unroll
            for (int half = 0; half < 2; half++) {
                float2 bv[4];
#pragma unroll
                for (int q = 0; q < 4; q++)
                    bv[q] = __ldg(&Bb[kt * 512 + (half * 4 + q) * 32]);
#pragma unroll
                for (int q = 0; q < 4; q++) {
                    unsigned b[2] = { __float_as_uint(bv[q].x), __float_as_uint(bv[q].y) };
                    mma_tf32(acc[half * 4 + q], a0, b);
                }
            }
        }
    }
    __syncthreads();   // all reads of es_h done -> sout overlay safe

    {
        const int r0 = m0 + g, r1 = m0 + 8 + g;
#pragma unroll
        for (int nt = 0; nt < 8; nt++) {
            int c0 = nh * 64 + nt * 8 + tig * 2;
            float b0 = bes_sh[c0], b1 = bes_sh[c0 + 1];
            float v0 = acc[nt][0] + b0, v1 = acc[nt][1] + b1;
            float v2 = acc[nt][2] + b0, v3 = acc[nt][3] + b1;
            v0 *= sigf(v0); v1 *= sigf(v1); v2 *= sigf(v2); v3 *= sigf(v3);
            *(float2*)(sout + r0 * SPAD + c0) = make_float2(v0, v1);
            *(float2*)(sout + r1 * SPAD + c0) = make_float2(v2, v3);
            if (nh == 0 && nt < 2) {
                gate_sh[r0 * 16 + c0]     = sigf(v0);
                gate_sh[r0 * 16 + c0 + 1] = sigf(v1);
                gate_sh[r1 * 16 + c0]     = sigf(v2);
                gate_sh[r1 * 16 + c0 + 1] = sigf(v3);
            }
        }
    }
    __syncthreads();

#pragma unroll
    for (int j = 0; j < 8; j++) {
        int el = w * 8 + j;
        if (el >= nE) break;
        float4 s = *(const float4*)(sout + el * SPAD + 4 * lane);
        red4(g_agg + (size_t)dst_sh[el] * 176 + 4 * lane, s);
    }

    if (tid < 192) {
        const int q   = tid >> 4;
        const int sub = tid & 15;
        float w0[4], w1[4], w2[4], bq[4];
        int   gi[4];
#pragma unroll
        for (int i = 0; i < 4; i++) {
            int o = 4 * q + i;
            w0[i] = wev_sh[o * 3 + 0]; w1[i] = wev_sh[o * 3 + 1];
            w2[i] = wev_sh[o * 3 + 2]; bq[i] = bev_sh[o];
            gi[i] = o / 3;
        }
#pragma unroll
        for (int j = 0; j < 4; j++) {
            int el = sub + 16 * j;
            if (el >= nE) continue;
            float e0v = ev_sh[el * 3 + 0], e1v = ev_sh[el * 3 + 1], e2v = ev_sh[el * 3 + 2];
            float4 v; float* vp = (float*)&v;
#pragma unroll
            for (int i = 0; i < 4; i++) {
                float val = fmaf(w0[i], e0v, fmaf(w1[i], e1v, fmaf(w2[i], e2v, bq[i])));
                vp[i] = val * gate_sh[el * 16 + gi[i]];
            }
            red4(g_agg + (size_t)dst_sh[el] * 176 + 128 + 4 * q, v);
        }
    }
}

// ---------------------------------------------------------------------------
// Node kernel (launch #4 -> ncu): persistent, 512 threads, tf32 mma, B from
// L2, single-tf32 A; __launch_bounds__(512,3) forces <=41 regs -> 3 blk/SM.
// ---------------------------------------------------------------------------
#define XPAD 132
#define NODE_SMEM_FLOATS 17248

__global__ __launch_bounds__(512, 3) void node_kernel(
    const float* __restrict__ node_s, const float* __restrict__ node_v,
    const float* __restrict__ ln_g, const float* __restrict__ ln_b,
    const float* __restrict__ bns, const float* __restrict__ brs,
    const float* __restrict__ bnv, const float* __restrict__ brv,
    float* __restrict__ out, int Nn)
{
    extern __shared__ float smf[];
    float* wVT  = smf;                 // 4608
    float* xh   = wVT + 4608;          // 4224  (x_s tf32 -> wns-result)
    float* sh   = xh + 4224;           // 4224  (raw -> s_n tf32 -> wrs-result)
    float* vn   = sh + 4224;           // 1536
    float* xv   = vn + 1536;           // 1536
    float* gate = xv + 1536;           // 512
    float* lng  = gate + 512;
    float* lnb  = lng + 128;
    float* bnsS = lnb + 128;
    float* brsS = bnsS + 128;
    float* bnvS = brsS + 128;
    float* brvS = bnvS + 48;

    const int tid  = threadIdx.x;
    const int lane = tid & 31;
    const int w    = tid >> 5;
    const int g    = lane >> 2;
    const int tig  = lane & 3;

    for (int i = tid; i < 4608; i += 512) wVT[i] = g_wVT[i];
    if (tid < 128) { lng[tid] = ln_g[tid]; lnb[tid] = ln_b[tid];
                     bnsS[tid] = bns[tid]; brsS[tid] = brs[tid]; }
    if (tid < 48)  { bnvS[tid] = bnv[tid]; brvS[tid] = brv[tid]; }

    const int mstrip = w >> 3;
    const int nstrip = w & 7;
    const int m0     = mstrip * 16;
    const bool wnsP  = (nstrip < 4);
    const float2* Bb = g_wB + (nstrip * 4) * 32 + lane;   // global, L2-resident

    const int ntiles = (Nn + 31) / 32;
    for (int tile = blockIdx.x; tile < ntiles; tile += gridDim.x) {
        const int n0t = tile * 32;
        const int nN  = min(32, Nn - n0t);
        __syncthreads();

        for (int i = tid; i < 4096; i += 512) {
            int r = i >> 7, c = i & 127;
            sh[r * XPAD + c] = (i < nN * 128) ? node_s[(size_t)n0t * 128 + i] : 0.f;
        }
        for (int i = tid; i < 1536; i += 512)
            vn[i] = (i < nN * 48) ? node_v[(size_t)n0t * 48 + i] : 0.f;
        __syncthreads();

        for (int q = 0; q < 2; q++) {
            int r = w * 2 + q;
            int n = n0t + r;
            const float* row = sh + r * XPAD;
            float a = row[lane] + row[lane + 32] + row[lane + 64] + row[lane + 96];
#pragma unroll
            for (int o = 16; o; o >>= 1) a += __shfl_xor_sync(0xffffffffu, a, o);
            float mu = a * (1.f / 128.f);
            float d0 = row[lane] - mu, d1 = row[lane + 32] - mu;
            float d2 = row[lane + 64] - mu, d3 = row[lane + 96] - mu;
            float vv = d0 * d0 + d1 * d1 + d2 * d2 + d3 * d3;
#pragma unroll
            for (int o = 16; o; o >>= 1) vv += __shfl_xor_sync(0xffffffffu, vv, o);
            float rs = rsqrtf(vv * (1.f / 128.f) + 1e-5f);

            const float* vrow = vn + r * 48;
            float x0 = vrow[lane];
            float x1 = (lane < 16) ? vrow[32 + lane] : 0.f;
            float sq = x0 * x0 + x1 * x1;
#pragma unroll
            for (int o = 16; o; o >>= 1) sq += __shfl_xor_sync(0xffffffffu, sq, o);
            float vr = rsqrtf(sq * (1.f / 16.f) + 1e-8f);

            float invden = 0.f;
            const float* aggr = g_agg + (size_t)n * 176;
            if (r < nN) invden = __fdividef(1.f, fmaxf(g_cnt[n], 1.f));

#pragma unroll
            for (int jj = 0; jj < 4; jj++) {
                int c = lane + 32 * jj;
                float x = (row[c] - mu) * rs * lng[c] + lnb[c];
                float xa = x;
                if (r < nN) xa = x + aggr[c] * invden;
                sh[r * XPAD + c] = tf32f(x);       // s_n (tf32, wrs path)
                xh[r * XPAD + c] = tf32f(xa);      // x_s (tf32, wns path)
            }
            {
                float x = x0 * vr;
                float xa = x;
                if (r < nN) xa = x + aggr[128 + lane] * invden;
                vn[r * 48 + lane] = x;
                xv[r * 48 + lane] = xa;
                if (lane < 16) {
                    float y = x1 * vr;
                    float ya = y;
                    if (r < nN) ya = y + aggr[128 + 32 + lane] * invden;
                    vn[r * 48 + 32 + lane] = y;
                    xv[r * 48 + 32 + lane] = ya;
                }
            }
        }
        __syncthreads();

        float acc[4][4];
#pragma unroll
        for (int nt = 0; nt < 4; nt++)
#pragma unroll
            for (int i = 0; i < 4; i++) acc[nt][i] = 0.f;

        {
            const float* A = wnsP ? xh : sh;
            const int arow = (m0 + g) * XPAD + tig;
#pragma unroll 4
            for (int kt = 0; kt < 16; kt++) {
                const int ko = kt * 8;
                float2 bv[4];
#pragma unroll
                for (int nt = 0; nt < 4; nt++) bv[nt] = __ldg(&Bb[kt * 1024 + nt * 32]);
                unsigned a0[4];
                a0[0] = __float_as_uint(A[arow + ko]);
                a0[1] = __float_as_uint(A[arow + 8 * XPAD + ko]);
                a0[2] = __float_as_uint(A[arow + ko + 4]);
                a0[3] = __float_as_uint(A[arow + 8 * XPAD + ko + 4]);
#pragma unroll
                for (int nt = 0; nt < 4; nt++) {
                    unsigned b[2] = { __float_as_uint(bv[nt].x), __float_as_uint(bv[nt].y) };
                    mma_tf32(acc[nt], a0, b);
                }
            }
        }
        __syncthreads();

        {
            const int r0 = m0 + g, r1 = m0 + 8 + g;
#pragma unroll
            for (int nt = 0; nt < 4; nt++) {
                int o = nstrip * 32 + nt * 8 + tig * 2;
                if (wnsP) {
                    float b0v = bnsS[o], b1v = bnsS[o + 1];
                    float v0 = acc[nt][0] + b0v, v1 = acc[nt][1] + b1v;
                    float v2 = acc[nt][2] + b0v, v3 = acc[nt][3] + b1v;
                    v0 *= sigf(v0); v1 *= sigf(v1); v2 *= sigf(v2); v3 *= sigf(v3);
                    xh[r0 * XPAD + o]     = v0;
                    xh[r0 * XPAD + o + 1] = v1;
                    xh[r1 * XPAD + o]     = v2;
                    xh[r1 * XPAD + o + 1] = v3;
                    if (o < 16) {
                        gate[r0 * 16 + o]     = sigf(v0);
                        gate[r0 * 16 + o + 1] = sigf(v1);
                        gate[r1 * 16 + o]     = sigf(v2);
                        gate[r1 * 16 + o + 1] = sigf(v3);
                    }
                } else {
                    int oc = o - 128;
                    float b0v = brsS[oc], b1v = brsS[oc + 1];
                    sh[r0 * XPAD + oc]     = acc[nt][0] + b0v;
                    sh[r0 * XPAD + oc + 1] = acc[nt][1] + b1v;
                    sh[r1 * XPAD + oc]     = acc[nt][2] + b0v;
                    sh[r1 * XPAD + oc + 1] = acc[nt][3] + b1v;
                }
            }
        }
        __syncthreads();

        for (int i = tid; i < nN * 128; i += 512) {
            int r = i >> 7, c = i & 127;
            out[(size_t)n0t * 128 + i] = xh[r * XPAD + c] + sh[r * XPAD + c];
        }

        for (int p = tid; p < nN * 48; p += 512) {
            int r = p / 48, o = p % 48;
            const float* xvr = xv + r * 48;
            const float* vnr = vn + r * 48;
            float a = 0.f, bq = 0.f;
#pragma unroll 4
            for (int k = 0; k < 48; k++) {
                a  = fmaf(xvr[k], wVT[k * 96 + o],      a);
                bq = fmaf(vnr[k], wVT[k * 96 + 48 + o], bq);
            }
            float val = (a + bnvS[o]) * gate[r * 16 + o / 3] + bq + brvS[o];
            out[(size_t)Nn * 128 + (size_t)n0t * 48 + p] = val;
        }
    }
}

// ---------------------------------------------------------------------------
extern "C" void kernel_launch(void* const* d_in, const int* in_sizes, int n_in,
                              void* d_out, int out_size)
{
    const float* node_s = (const float*)d_in[0];
    const float* node_v = (const float*)d_in[1];
    const int*   ei     = (const int*)  d_in[2];
    const float* edge_s = (const float*)d_in[3];
    const float* edge_v = (const float*)d_in[4];
    const float* ln_g   = (const float*)d_in[5];
    const float* ln_b   = (const float*)d_in[6];
    const float* wes    = (const float*)d_in[7];
    const float* bes    = (const float*)d_in[8];
    const float* wev    = (const float*)d_in[9];
    const float* bev    = (const float*)d_in[10];
    const float* wns    = (const float*)d_in[11];
    const float* bns    = (const float*)d_in[12];
    const float* wnv    = (const float*)d_in[13];
    const float* bnv    = (const float*)d_in[14];
    const float* wrs    = (const float*)d_in[15];
    const float* brs    = (const float*)d_in[16];
    const float* wrv    = (const float*)d_in[17];
    const float* brv    = (const float*)d_in[18];

    const int N = in_sizes[0] / 128;
    const int E = in_sizes[3] / 32;

    cudaFuncSetAttribute(node_kernel, cudaFuncAttributeMaxDynamicSharedMemorySize,
                         NODE_SMEM_FLOATS * sizeof(float));

    prep_kernel<<<(N + 255) / 256, 256>>>(wes, wns, wrs, wnv, wrv, N);  // #1 (+cnt)
    zero_agg_kernel<<<(N * 44 + 255) / 256, 256>>>(N);                  // #2
    edge_kernel<<<(E + TE - 1) / TE, 256>>>(edge_s, edge_v, ei,         // #3
                                            bes, wev, bev, E);
    node_kernel<<<456, 512, NODE_SMEM_FLOATS * sizeof(float)>>>(        // #4 (ncu)
        node_s, node_v, ln_g, ln_b, bns, brs, bnv, brv, (float*)d_out, N);
}